// round 11
// baseline (speedup 1.0000x reference)
#include <cuda_runtime.h>
#include <cuda_bf16.h>
#include <cstdint>

#define BINS   30
#define TPB    256
#define GRID   296     // 2 blocks per SM
#define TILE   1024    // elements per tile (12 KB: 8 KB x + 4 KB t)
#define STAGES 4
#define EPT    4       // elements per thread per tile (thread owns 4*tid..4*tid+3)

// dynamic smem layout (bytes):
//   [0, 61440)        hist: float2[BINS*TPB]
//   [61440, +32768)   xs:   float2[STAGES*TILE]
//   [94208, +16384)   ts:   int[STAGES*TILE]
#define SMEM_HIST 0
#define SMEM_XS   61440
#define SMEM_TS   (SMEM_XS + STAGES * TILE * 8)
#define SMEM_TOTAL (SMEM_TS + STAGES * TILE * 4)   // 110592 B = 108 KB

__device__ float2 g_part[GRID * BINS];
__device__ unsigned int g_ctr = 0;

__device__ __forceinline__ float rcp_approx(float x) {
    float r;
    asm("rcp.approx.f32 %0, %1;" : "=f"(r) : "f"(x));
    return r;
}

__device__ __forceinline__ void cp_async16(uint32_t saddr, const void* gptr) {
    asm volatile("cp.async.cg.shared.global [%0], [%1], 16;" :: "r"(saddr), "l"(gptr));
}
__device__ __forceinline__ void cp_commit() {
    asm volatile("cp.async.commit_group;");
}
template <int N>
__device__ __forceinline__ void cp_wait() {
    asm volatile("cp.async.wait_group %0;" :: "n"(N));
}

// math only: u = x_other - x_true; bin = trunc(30*sigmoid(u)); ce = log(1+e^u).
__device__ __forceinline__ void ghm_math(float x0, float x1, int t,
                                         int* boff, float* ce) {
    float diff = x1 - x0;
    float u = __int_as_float(__float_as_int(diff) ^ (t << 31));
    float e = __expf(u);
    float s = 1.0f + e;
    float r = rcp_approx(s);
    float bin_f = fmaf(r, -30.0f, 30.0f);        // 30*g
    bin_f = fminf(bin_f, 29.0f);
    *boff = (int)bin_f * TPB;
    *ce = __log2f(s) * 0.69314718056f;
}

// thread-owned copy: this thread's 4 elements of tile T into stage st.
// x: float4 indices 2*tid, 2*tid+1 ; t: int4 index tid. Always commits.
__device__ __forceinline__ void issue_tile(const float4* __restrict__ x4,
                                           const int4* __restrict__ t4,
                                           int T, int NT, int st, int tid,
                                           uint32_t xs_s, uint32_t ts_s) {
    if (T < NT) {
        const float4* xg = x4 + (size_t)T * (TILE / 2) + 2 * tid;
        uint32_t xd = xs_s + (uint32_t)(st * TILE) * 8u + (uint32_t)tid * 32u;
        cp_async16(xd,       xg);
        cp_async16(xd + 16u, xg + 1);
        const int4* tg = t4 + (size_t)T * (TILE / 4) + tid;
        uint32_t td = ts_s + (uint32_t)(st * TILE) * 4u + (uint32_t)tid * 16u;
        cp_async16(td, tg);
    }
    cp_commit();
}

__global__ void __launch_bounds__(TPB, 2) ghm_fused(const float4* __restrict__ x4,
                                                    const int4* __restrict__ t4,
                                                    const float2* __restrict__ x2,
                                                    const int* __restrict__ tgt,
                                                    int B,
                                                    float* __restrict__ out,
                                                    int out_size) {
    extern __shared__ char smem[];
    float2* hist = (float2*)(smem + SMEM_HIST);
    float2* xs   = (float2*)(smem + SMEM_XS);
    int*    ts   = (int*)(smem + SMEM_TS);
    uint32_t xs_s = (uint32_t)__cvta_generic_to_shared(xs);
    uint32_t ts_s = (uint32_t)__cvta_generic_to_shared(ts);

    int tid = threadIdx.x;
    int bx  = blockIdx.x;

    #pragma unroll
    for (int b = 0; b < BINS; b++) hist[b * TPB + tid] = make_float2(0.0f, 0.0f);
    __syncthreads();

    float2* hrow = &hist[tid];

    int NT = B / TILE;

    // prologue: fill all stages (own region only)
    #pragma unroll
    for (int p = 0; p < STAGES; p++)
        issue_tile(x4, t4, bx + p * GRID, NT, p, tid, xs_s, ts_s);

    // barrier-free steady state; refill issued as soon as the stage's data
    // is consumed into registers (LDGSTS write lands >=600cyc later: safe).
    int st = 0;
    for (int k = 0; ; k++) {
        int T = bx + k * GRID;
        if (T >= NT) break;

        cp_wait<STAGES - 1>();   // own copies for tile k complete -> self-visible

        const float4* xst = (const float4*)(xs + st * TILE) + 2 * tid;
        const int4*   tst = (const int4*)(ts + st * TILE) + tid;
        float4 xa = xst[0];
        float4 xb = xst[1];
        int4   tv = tst[0];

        // early refill: stage st is free from this thread's perspective
        issue_tile(x4, t4, bx + (k + STAGES) * GRID, NT, st, tid, xs_s, ts_s);
        st = (st + 1 == STAGES) ? 0 : st + 1;

        int   boff[EPT];
        float cev[EPT];
        ghm_math(xa.x, xa.y, tv.x, &boff[0], &cev[0]);
        ghm_math(xa.z, xa.w, tv.y, &boff[1], &cev[1]);
        ghm_math(xb.x, xb.y, tv.z, &boff[2], &cev[2]);
        ghm_math(xb.z, xb.w, tv.w, &boff[3], &cev[3]);

        #pragma unroll
        for (int j = 0; j < EPT; j++) {
            float2 h = hrow[boff[j]];
            h.x += 1.0f;
            h.y += cev[j];
            hrow[boff[j]] = h;
        }
    }
    cp_wait<0>();

    // tail (B % TILE == 0 for this shape, kept for generality)
    int gt = bx * TPB + tid;
    for (int j = NT * TILE + gt; j < B; j += GRID * TPB) {
        float2 xv = x2[j];
        int bo; float cv;
        ghm_math(xv.x, xv.y, tgt[j], &bo, &cv);
        float2 h = hrow[bo];
        h.x += 1.0f; h.y += cv;
        hrow[bo] = h;
    }

    __syncthreads();

    // tree-reduce columns per bin
    for (int s = TPB / 2; s > 0; s >>= 1) {
        if (tid < s) {
            #pragma unroll
            for (int b = 0; b < BINS; b++) {
                float2 p = hist[b * TPB + tid];
                float2 q = hist[b * TPB + tid + s];
                p.x += q.x; p.y += q.y;
                hist[b * TPB + tid] = p;
            }
        }
        __syncthreads();
    }

    // per-block partials + last-block finalize
    if (tid < BINS) g_part[bx * BINS + tid] = hist[tid * TPB];
    __threadfence();
    __syncthreads();

    __shared__ bool is_last;
    if (tid == 0) {
        unsigned prev = atomicAdd(&g_ctr, 1u);
        is_last = (prev == GRID - 1);
    }
    __syncthreads();
    if (!is_last) return;

    __threadfence();

    #pragma unroll
    for (int b = 0; b < BINS; b++) hist[b * TPB + tid] = make_float2(0.0f, 0.0f);
    __syncthreads();

    for (int i = tid; i < GRID * BINS; i += TPB) {
        float2 v = g_part[i];
        int b = i % BINS;
        float2 h = hrow[b * TPB];
        h.x += v.x; h.y += v.y;
        hrow[b * TPB] = h;
    }
    __syncthreads();

    for (int s = TPB / 2; s > 0; s >>= 1) {
        if (tid < s) {
            #pragma unroll
            for (int b = 0; b < BINS; b++) {
                float2 p = hist[b * TPB + tid];
                float2 q = hist[b * TPB + tid + s];
                p.x += q.x; p.y += q.y;
                hist[b * TPB + tid] = p;
            }
        }
        __syncthreads();
    }

    if (tid < 32) {
        float cnt = (tid < BINS) ? hist[tid * TPB].x : 0.0f;
        float ces = (tid < BINS) ? hist[tid * TPB].y : 0.0f;
        float nz   = (cnt > 0.0f) ? 1.0f : 0.0f;
        float term = (cnt > 0.0f) ? ces / (0.25f * cnt) : 0.0f;
        #pragma unroll
        for (int o = 16; o > 0; o >>= 1) {
            nz   += __shfl_xor_sync(0xFFFFFFFFu, nz,   o);
            term += __shfl_xor_sync(0xFFFFFFFFu, term, o);
        }
        if (tid == 0) {
            float loss = term / fmaxf(nz, 1.0f);
            for (int i = 0; i < out_size; i++) out[i] = loss;
            g_ctr = 0;  // reset for next graph replay
        }
    }
}

extern "C" void kernel_launch(void* const* d_in, const int* in_sizes, int n_in,
                              void* d_out, int out_size) {
    const float* x   = (const float*)d_in[0];
    const int*   tgt = (const int*)d_in[1];
    int B = in_sizes[1];   // target element count == batch size

    cudaFuncSetAttribute(ghm_fused, cudaFuncAttributeMaxDynamicSharedMemorySize, SMEM_TOTAL);
    ghm_fused<<<GRID, TPB, SMEM_TOTAL>>>((const float4*)x, (const int4*)tgt,
                                         (const float2*)x, tgt, B,
                                         (float*)d_out, out_size);
}